// round 15
// baseline (speedup 1.0000x reference)
#include <cuda_runtime.h>
#include <cuda_bf16.h>
#include <cstdint>

#define BATCH    128
#define WTOT     8192
#define DDIM     64
#define SSPLIT   4
#define WSEG     (WTOT / SSPLIT)     // 2048
#define WC       128                 // w per staged tile
#define NTILES   (WSEG / WC)         // 16
#define NTHREADS 512
#define KSTEPS   8                   // 128 w / k16 per mma
#define NSLOTS   4
#define TILE_B   (WC * 128)          // 16384 bytes per bf16 tile
#define SM_SUMS  (NSLOTS * TILE_B)   // 65536
#define DYN_SMEM (SM_SUMS + 4096)    // + sums (256 * float4)

// Scratch partials (no allocations allowed)
__device__ float g_part[BATCH][SSPLIT][DDIM * DDIM];   // upper 16x16 blocks only
__device__ float s_part[BATCH][SSPLIT][DDIM];
__device__ unsigned int done_cnt[BATCH];               // zero-init; reset by finalizer

__device__ __forceinline__ uint32_t smem_u32(const void* p) {
    uint32_t a;
    asm("{ .reg .u64 t; cvta.to.shared.u64 t, %1; cvt.u32.u64 %0, t; }" : "=r"(a) : "l"(p));
    return a;
}
__device__ __forceinline__ uint32_t cvt2(float hi, float lo) {
    uint32_t r; asm("cvt.rn.bf16x2.f32 %0, %1, %2;" : "=r"(r) : "f"(hi), "f"(lo)); return r;
}
__device__ __forceinline__ void sts64(uint32_t addr, uint32_t r0, uint32_t r1) {
    asm volatile("st.shared.v2.b32 [%0], {%1, %2};" :: "r"(addr), "r"(r0), "r"(r1) : "memory");
}
__device__ __forceinline__ void ldsm4t(uint32_t& r0, uint32_t& r1, uint32_t& r2, uint32_t& r3,
                                       uint32_t addr) {
    asm volatile("ldmatrix.sync.aligned.m8n8.x4.trans.shared.b16 {%0,%1,%2,%3}, [%4];"
                 : "=r"(r0), "=r"(r1), "=r"(r2), "=r"(r3) : "r"(addr));
}
__device__ __forceinline__ void mma16816(float* d,
                                         uint32_t a0, uint32_t a1, uint32_t a2, uint32_t a3,
                                         uint32_t b0, uint32_t b1) {
    asm volatile(
        "mma.sync.aligned.m16n8k16.row.col.f32.bf16.bf16.f32 "
        "{%0,%1,%2,%3}, {%4,%5,%6,%7}, {%8,%9}, {%0,%1,%2,%3};"
        : "+f"(d[0]), "+f"(d[1]), "+f"(d[2]), "+f"(d[3])
        : "r"(a0), "r"(a1), "r"(a2), "r"(a3), "r"(b0), "r"(b1));
}
#define BAR_SYNC(id)   asm volatile("bar.sync %0, %1;"   :: "r"(id), "r"(NTHREADS) : "memory")
#define BAR_ARRIVE(id) asm volatile("bar.arrive %0, %1;" :: "r"(id), "r"(NTHREADS) : "memory")

// bf16 mma tile: [w][d], 128 B per row, XOR-swizzled by ((w&7)<<4).
#define SWZ(w, d2bytes) ((uint32_t)((w) * 128 + (d2bytes)) ^ (((uint32_t)(w) & 7u) << 4))

__global__ __launch_bounds__(NTHREADS, 2)
void gram_kernel(const float* __restrict__ x, float* __restrict__ out) {
    extern __shared__ __align__(16) uint8_t dynsmem[];     // ring + sums
    __shared__ unsigned int lastflag;

    const int tid  = threadIdx.x;
    const int wid  = tid >> 5;
    const int lane = tid & 31;
    const int s = blockIdx.x;
    const int b = blockIdx.y;

    const uint32_t stg = smem_u32(dynsmem);
    float4* sums = (float4*)(dynsmem + SM_SUMS);

    const float4* gp = (const float4*)(x + ((long)b * WTOT + (long)s * WSEG) * DDIM);

    if (wid >= 8) {
        // ================= PRODUCER: warps 8-15 (256 threads) =================
        const int ptid = tid - 256;
        const int d0 = 4 * (ptid & 15);          // feature quad
        const int w0 = ptid >> 4;                // 0..15
        float sum0 = 0.f, sum1 = 0.f, sum2 = 0.f, sum3 = 0.f;

        float4 v[8];
#pragma unroll
        for (int i = 0; i < 8; i++) v[i] = gp[ptid + 256 * i];

#pragma unroll 1
        for (int c = 0; c < NTILES; c++) {
            const int slot = c & (NSLOTS - 1);
            const uint32_t sbase = stg + (uint32_t)(slot * TILE_B);
            const bool more = (c + 1 < NTILES);
            const float4* gnext = gp + (c + 1) * 2048;

            if (c >= NSLOTS) BAR_SYNC(5 + slot);          // wait slot empty
#pragma unroll
            for (int i = 0; i < 8; i++) {
                uint32_t r0 = cvt2(v[i].y, v[i].x);
                uint32_t r1 = cvt2(v[i].w, v[i].z);
                sum0 += v[i].x; sum1 += v[i].y; sum2 += v[i].z; sum3 += v[i].w;
                const int w = w0 + 16 * i;
                sts64(sbase + SWZ(w, d0 * 2), r0, r1);
                if (more) v[i] = gnext[ptid + 256 * i];
            }
            __threadfence_block();                        // STS visible before arrive
            BAR_ARRIVE(1 + slot);                         // slot full
        }

        // column sums -> smem
        const int q = ptid & 15, p = ptid >> 4;
        sums[(q << 4) | p] = make_float4(sum0, sum1, sum2, sum3);
    } else {
        // ================= CONSUMER: warps 0-7 (MMA) =================
        int rA, cAb;
        if (wid < 4)      { rA = wid; cAb = wid;     }
        else if (wid < 7) { rA = 0;   cAb = wid - 3; }
        else              { rA = 1;   cAb = 2;       }
        const bool dual = (wid < 2);
        const int rB = wid + 1, cBb = 3;   // extra blocks (1,3), (2,3)

        const int kA = (lane & 7) + ((lane & 16) >> 1);
        const int kB = (lane & 7) + (lane & 8);
        const uint32_t swx = ((uint32_t)lane & 7u) << 4;
        const int laneA = lane & 8;
        const int laneB = (lane & 16) >> 1;
        const uint32_t oA1 = (uint32_t)(kA * 128 + (16 * rA + laneA) * 2) ^ swx;
        const uint32_t oB1 = (uint32_t)(kB * 128 + (16 * cAb + laneB) * 2) ^ swx;
        const uint32_t oA2 = (uint32_t)(kA * 128 + (16 * rB + laneA) * 2) ^ swx;
        const uint32_t oB2 = (uint32_t)(kB * 128 + (16 * cBb + laneB) * 2) ^ swx;

        float acc1[2][4], acc2[2][4];
#pragma unroll
        for (int t = 0; t < 2; t++)
#pragma unroll
            for (int r = 0; r < 4; r++) { acc1[t][r] = 0.f; acc2[t][r] = 0.f; }

#pragma unroll 1
        for (int c = 0; c < NTILES; c++) {
            const int slot = c & (NSLOTS - 1);
            const uint32_t sbase = stg + (uint32_t)(slot * TILE_B);

            BAR_SYNC(1 + slot);                           // wait slot full
#pragma unroll
            for (int ks = 0; ks < KSTEPS; ks++) {
                const uint32_t kb = sbase + (uint32_t)(ks * 2048);
                uint32_t a0, a1, a2, a3, b0, b1, b2, b3;
                ldsm4t(a0, a1, a2, a3, kb + oA1);
                ldsm4t(b0, b1, b2, b3, kb + oB1);
                mma16816(acc1[0], a0, a1, a2, a3, b0, b1);
                mma16816(acc1[1], a0, a1, a2, a3, b2, b3);
                if (dual) {
                    ldsm4t(a0, a1, a2, a3, kb + oA2);
                    ldsm4t(b0, b1, b2, b3, kb + oB2);
                    mma16816(acc2[0], a0, a1, a2, a3, b0, b1);
                    mma16816(acc2[1], a0, a1, a2, a3, b2, b3);
                }
            }
            // in-order issue: arrive comes after the dependent MMAs have issued,
            // which implies the LDSM smem reads completed.
            if (c + NSLOTS < NTILES) BAR_ARRIVE(5 + slot);   // slot empty
        }

        // ---- write Gram partial blocks (upper triangle only) ----
        const int g = lane >> 2;
        const int col2 = 2 * (lane & 3);
        float* gpart = &g_part[b][s][0];
#pragma unroll
        for (int t = 0; t < 2; t++) {
            const int jcol = 16 * cAb + 8 * t + col2;
            *(float2*)&gpart[(16 * rA + g) * DDIM + jcol]     = make_float2(acc1[t][0], acc1[t][1]);
            *(float2*)&gpart[(16 * rA + g + 8) * DDIM + jcol] = make_float2(acc1[t][2], acc1[t][3]);
        }
        if (dual) {
#pragma unroll
            for (int t = 0; t < 2; t++) {
                const int jcol = 16 * cBb + 8 * t + col2;
                *(float2*)&gpart[(16 * rB + g) * DDIM + jcol]     = make_float2(acc2[t][0], acc2[t][1]);
                *(float2*)&gpart[(16 * rB + g + 8) * DDIM + jcol] = make_float2(acc2[t][2], acc2[t][3]);
            }
        }
    }

    __syncthreads();   // producers' sums + consumers' g_part stores ordered

    if (tid < DDIM) {
        const int q = tid >> 2, r = tid & 3;
        const float* sp = (const float*)sums;
        float a = 0.f;
#pragma unroll
        for (int p = 0; p < 16; p++) a += sp[(((q << 4) | p) << 2) + r];
        s_part[b][s][tid] = a;
    }

    // ---- arrival protocol: last CTA of this batch finalizes ----
    __threadfence();
    __syncthreads();
    if (tid == 0) {
        unsigned int old = atomicAdd(&done_cnt[b], 1u);
        lastflag = (old == SSPLIT - 1);
        if (lastflag) done_cnt[b] = 0;   // reset for next graph replay
    }
    __syncthreads();
    if (!lastflag) return;
    __threadfence();   // acquire: make peers' partials visible

    // ================= inline finalize (smem reuse) =================
    float* cov  = (float*)dynsmem;               // 16 KB
    float* ssum = (float*)sums;                  // 64 floats
    float* stdv = ssum + DDIM;                   // 64 floats

    for (int idx = tid; idx < DDIM * DDIM; idx += NTHREADS) {
        const int i = idx >> 6, j = idx & 63;
        const int src = ((i >> 4) <= (j >> 4)) ? idx : (j * DDIM + i);  // mirror lower
        float a = 0.f;
#pragma unroll
        for (int ss = 0; ss < SSPLIT; ss++) a += __ldcg(&g_part[b][ss][src]);
        cov[idx] = a;
    }
    __syncthreads();   // sums smem repurposed below
    if (tid < DDIM) {
        float a = 0.f;
#pragma unroll
        for (int ss = 0; ss < SSPLIT; ss++) a += __ldcg(&s_part[b][ss][tid]);
        ssum[tid] = a;
    }
    __syncthreads();

    const float invW  = 1.0f / (float)WTOT;
    const float invW1 = 1.0f / (float)(WTOT - 1);

    if (tid < DDIM) {
        float Si = ssum[tid];
        float cc = (cov[tid * DDIM + tid] - Si * Si * invW) * invW1;
        stdv[tid] = sqrtf(cc) + 1e-8f;
    }
    __syncthreads();

    if (tid < DDIM) {
        const int i = tid;
        float Si = ssum[i];
        float inv_si = 1.0f / stdv[i];
        float cnt = 0.f;
#pragma unroll 8
        for (int j = 0; j < DDIM; j++) {
            float cc = (cov[i * DDIM + j] - Si * ssum[j] * invW) * invW1;
            float corr = cc * inv_si / stdv[j];
            if (fabsf(corr) > 0.3f) cnt += 1.0f;
        }
        out[b * DDIM + i] = cnt - 1.0f;
    }
}

extern "C" void kernel_launch(void* const* d_in, const int* in_sizes, int n_in,
                              void* d_out, int out_size) {
    const float* x = (const float*)d_in[0];
    float* out = (float*)d_out;

    cudaFuncSetAttribute(gram_kernel, cudaFuncAttributeMaxDynamicSharedMemorySize, DYN_SMEM);

    dim3 grid(SSPLIT, BATCH);
    gram_kernel<<<grid, NTHREADS, DYN_SMEM>>>(x, out);
}

// round 16
// speedup vs baseline: 1.0659x; 1.0659x over previous
#include <cuda_runtime.h>
#include <cuda_bf16.h>
#include <cstdint>

#define BATCH    128
#define WTOT     8192
#define DDIM     64
#define SSPLIT   4
#define WSEG     (WTOT / SSPLIT)     // 2048
#define WC       64                  // w per staged tile
#define NTILES   (WSEG / WC)         // 32
#define NTHREADS 256
#define KSTEPS   4                   // 64 w / k16 per mma

// Scratch partials (no allocations allowed)
__device__ float g_part[BATCH][SSPLIT][DDIM * DDIM];   // upper 16x16 blocks (+2 junk lower)
__device__ float s_part[BATCH][SSPLIT][DDIM];
__device__ unsigned int done_cnt[BATCH];               // zero-init; reset by finalizer

__device__ __forceinline__ uint32_t smem_u32(const void* p) {
    uint32_t a;
    asm("{ .reg .u64 t; cvta.to.shared.u64 t, %1; cvt.u32.u64 %0, t; }" : "=r"(a) : "l"(p));
    return a;
}
__device__ __forceinline__ uint32_t cvt2(float hi, float lo) {
    uint32_t r; asm("cvt.rn.bf16x2.f32 %0, %1, %2;" : "=r"(r) : "f"(hi), "f"(lo)); return r;
}
__device__ __forceinline__ void sts64(uint32_t addr, uint32_t r0, uint32_t r1) {
    asm volatile("st.shared.v2.b32 [%0], {%1, %2};" :: "r"(addr), "r"(r0), "r"(r1) : "memory");
}
__device__ __forceinline__ float4 ldcs4(const float4* p) {
    float4 v;
    asm volatile("ld.global.cs.v4.f32 {%0,%1,%2,%3}, [%4];"
                 : "=f"(v.x), "=f"(v.y), "=f"(v.z), "=f"(v.w) : "l"(p));
    return v;
}
__device__ __forceinline__ void ldsm4t(uint32_t& r0, uint32_t& r1, uint32_t& r2, uint32_t& r3,
                                       uint32_t addr) {
    asm volatile("ldmatrix.sync.aligned.m8n8.x4.trans.shared.b16 {%0,%1,%2,%3}, [%4];"
                 : "=r"(r0), "=r"(r1), "=r"(r2), "=r"(r3) : "r"(addr));
}
__device__ __forceinline__ void mma16816(float* d,
                                         uint32_t a0, uint32_t a1, uint32_t a2, uint32_t a3,
                                         uint32_t b0, uint32_t b1) {
    asm volatile(
        "mma.sync.aligned.m16n8k16.row.col.f32.bf16.bf16.f32 "
        "{%0,%1,%2,%3}, {%4,%5,%6,%7}, {%8,%9}, {%0,%1,%2,%3};"
        : "+f"(d[0]), "+f"(d[1]), "+f"(d[2]), "+f"(d[3])
        : "r"(a0), "r"(a1), "r"(a2), "r"(a3), "r"(b0), "r"(b1));
}

// bf16 mma tile: [w][d], 128 B per row, XOR-swizzled by ((w&7)<<4).
#define SWZ(w, d2bytes) ((uint32_t)((w) * 128 + (d2bytes)) ^ (((uint32_t)(w) & 7u) << 4))

__global__ __launch_bounds__(NTHREADS, 4)
void gram_kernel(const float* __restrict__ x, float* __restrict__ out) {
    __shared__ __align__(16) uint8_t stage[2][WC * 128];   // 2 x 8 KB bf16 tiles
    __shared__ float4 sums[NTHREADS];                       // 4 KB
    __shared__ unsigned int lastflag;

    const int tid  = threadIdx.x;
    const int wid  = tid >> 5;
    const int lane = tid & 31;
    const int s = blockIdx.x;
    const int b = blockIdx.y;

    const uint32_t stg = smem_u32(&stage[0][0]);

    // Phase A role: chunk f = tid + 256*i -> w = (tid>>4) + 16*i, d-quad = tid&15
    const int d0 = 4 * (tid & 15);
    const int w0 = tid >> 4;                 // 0..15

    // ---- warp -> 16x32 slab covering the upper triangle ----
    // w0:(0,0) w1:(0,1) w2:(1,0) w3:(1,1) w4:(2,1) w5:(3,1)  [rows 16*rA, cols 32*cP]
    // Upper 16-blocks produced: row0 all; (1,1),(1,2),(1,3); (2,2),(2,3); (3,3). Extra
    // lower blocks (1,0),(3,2) are written but never read (finalize mirrors from upper).
    const int rA = (wid < 2) ? 0 : (wid < 4) ? 1 : (wid - 2);
    const int cP = (wid < 4) ? (wid & 1) : 1;
    const bool active = (wid < 6);

    const int kA = (lane & 7) + ((lane & 16) >> 1);
    const int kB = (lane & 7) + (lane & 8);
    const uint32_t swx = ((uint32_t)lane & 7u) << 4;
    const uint32_t oA  = (uint32_t)(kA * 128 + (16 * rA + (lane & 8)) * 2) ^ swx;
    const int colB0 = 32 * cP + ((lane & 16) >> 1);
    const uint32_t oB0 = (uint32_t)(kB * 128 + colB0 * 2) ^ swx;
    const uint32_t oB1 = (uint32_t)(kB * 128 + (colB0 + 16) * 2) ^ swx;

    const float4* gp = (const float4*)(x + ((long)b * WTOT + (long)s * WSEG) * DDIM);

    float acc[4][4];
#pragma unroll
    for (int t = 0; t < 4; t++)
#pragma unroll
        for (int r = 0; r < 4; r++) acc[t][r] = 0.f;

    float sum0 = 0.f, sum1 = 0.f, sum2 = 0.f, sum3 = 0.f;

    float4 v[4];
#pragma unroll
    for (int i = 0; i < 4; i++) v[i] = ldcs4(gp + tid + 256 * i);

#pragma unroll 1
    for (int c = 0; c < NTILES; c++) {
        const uint32_t sbase = stg + (uint32_t)((c & 1) * (WC * 128));
        const bool more = (c + 1 < NTILES);
        const float4* gnext = gp + (c + 1) * 1024;

        // ---- Phase A: consume v[i] (cvt + sums + STS), reissue LDG(c+1) inline ----
#pragma unroll
        for (int i = 0; i < 4; i++) {
            uint32_t r0 = cvt2(v[i].y, v[i].x);
            uint32_t r1 = cvt2(v[i].w, v[i].z);
            sum0 += v[i].x; sum1 += v[i].y; sum2 += v[i].z; sum3 += v[i].w;
            const int w = w0 + 16 * i;
            sts64(sbase + SWZ(w, d0 * 2), r0, r1);
            if (more) v[i] = ldcs4(gnext + tid + 256 * i);
        }
        __syncthreads();

        // ---- MMA: 16x32 slab per warp (warps 0-5) ----
        if (active) {
#pragma unroll
            for (int ks = 0; ks < KSTEPS; ks++) {
                const uint32_t kb = sbase + (uint32_t)(ks * 2048);
                uint32_t a0, a1, a2, a3, p0, p1, p2, p3, q0, q1, q2, q3;
                ldsm4t(a0, a1, a2, a3, kb + oA);
                ldsm4t(p0, p1, p2, p3, kb + oB0);
                ldsm4t(q0, q1, q2, q3, kb + oB1);
                mma16816(acc[0], a0, a1, a2, a3, p0, p1);
                mma16816(acc[1], a0, a1, a2, a3, p2, p3);
                mma16816(acc[2], a0, a1, a2, a3, q0, q1);
                mma16816(acc[3], a0, a1, a2, a3, q2, q3);
            }
        }
        // MMA(c) ordered before phaseA(c+2) overwrite by sync(c+1).
    }

    // ---- write Gram partial slab: rows [16rA,16rA+16) x cols [32cP,32cP+32) ----
    if (active) {
        const int g = lane >> 2;
        const int col2 = 2 * (lane & 3);
        float* gpart = &g_part[b][s][0];
#pragma unroll
        for (int t = 0; t < 4; t++) {
            const int jcol = 32 * cP + 8 * t + col2;
            *(float2*)&gpart[(16 * rA + g) * DDIM + jcol]     = make_float2(acc[t][0], acc[t][1]);
            *(float2*)&gpart[(16 * rA + g + 8) * DDIM + jcol] = make_float2(acc[t][2], acc[t][3]);
        }
    }

    // ---- column sums -> s_part ----
    {
        const int q = tid & 15, p = tid >> 4;      // p: 0..15
        sums[(q << 4) | p] = make_float4(sum0, sum1, sum2, sum3);
    }
    __syncthreads();
    if (tid < DDIM) {
        const int q = tid >> 2, r = tid & 3;
        const float* sp = (const float*)sums;
        float a = 0.f;
#pragma unroll
        for (int p = 0; p < 16; p++) a += sp[(((q << 4) | p) << 2) + r];
        s_part[b][s][tid] = a;
    }

    // ---- arrival protocol: last CTA of this batch finalizes ----
    __threadfence();
    __syncthreads();
    if (tid == 0) {
        unsigned int old = atomicAdd(&done_cnt[b], 1u);
        lastflag = (old == SSPLIT - 1);
        if (lastflag) done_cnt[b] = 0;   // reset for next graph replay
    }
    __syncthreads();
    if (!lastflag) return;
    __threadfence();   // acquire: make peers' partials visible

    // ================= inline finalize (smem reuse) =================
    float* cov  = (float*)&stage[0][0];          // 16 KB
    float* ssum = (float*)&sums[0];              // 64 floats
    float* stdv = ssum + DDIM;                   // 64 floats

    for (int idx = tid; idx < DDIM * DDIM; idx += NTHREADS) {
        const int i = idx >> 6, j = idx & 63;
        const int src = ((i >> 4) <= (j >> 4)) ? idx : (j * DDIM + i);  // mirror lower
        float a = 0.f;
#pragma unroll
        for (int ss = 0; ss < SSPLIT; ss++) a += __ldcg(&g_part[b][ss][src]);
        cov[idx] = a;
    }
    __syncthreads();   // sums smem repurposed below
    if (tid < DDIM) {
        float a = 0.f;
#pragma unroll
        for (int ss = 0; ss < SSPLIT; ss++) a += __ldcg(&s_part[b][ss][tid]);
        ssum[tid] = a;
    }
    __syncthreads();

    const float invW  = 1.0f / (float)WTOT;
    const float invW1 = 1.0f / (float)(WTOT - 1);

    if (tid < DDIM) {
        float Si = ssum[tid];
        float cc = (cov[tid * DDIM + tid] - Si * Si * invW) * invW1;
        stdv[tid] = sqrtf(cc) + 1e-8f;
    }
    __syncthreads();

    if (tid < DDIM) {
        const int i = tid;
        float Si = ssum[i];
        float inv_si = 1.0f / stdv[i];
        float cnt = 0.f;
#pragma unroll 8
        for (int j = 0; j < DDIM; j++) {
            float cc = (cov[i * DDIM + j] - Si * ssum[j] * invW) * invW1;
            float corr = cc * inv_si / stdv[j];
            if (fabsf(corr) > 0.3f) cnt += 1.0f;
        }
        out[b * DDIM + i] = cnt - 1.0f;
    }
}

extern "C" void kernel_launch(void* const* d_in, const int* in_sizes, int n_in,
                              void* d_out, int out_size) {
    const float* x = (const float*)d_in[0];
    float* out = (float*)d_out;

    dim3 grid(SSPLIT, BATCH);
    gram_kernel<<<grid, NTHREADS>>>(x, out);
}